// round 1
// baseline (speedup 1.0000x reference)
#include <cuda_runtime.h>
#include <cstdint>

// ---------------- problem constants ----------------
#define NNODES 50000
#define NEDGES 800000
#define NREL   8
#define HID    256
#define NBASES 30
#define KTOT   2304          // 8*256 relation cols + 256 self cols
#define MPAD   50048         // 391 * 128

// ---------------- device scratch (static, .bss zero-initialized) ----------------
__device__ int   g_deg[NNODES];
__device__ float g_deginv[NNODES];
__device__ int   g_rowptr[NNODES + 1];
__device__ int   g_cursor[NNODES];
__device__ int   g_edges[NEDGES];                    // packed (rel<<16)|src
__device__ float g_tmpx[(size_t)MPAD * KTOT];        // rows >= 50000 stay zero forever
__device__ float g_W[KTOT * HID];
__device__ float g_x1[(size_t)MPAD * HID];

// ---------------- setup kernels ----------------
__global__ void zero_deg_kernel() {
    int i = blockIdx.x * blockDim.x + threadIdx.x;
    if (i < NNODES) g_deg[i] = 0;
}

__global__ void hist_kernel(const int* __restrict__ dst) {
    int e = blockIdx.x * blockDim.x + threadIdx.x;
    if (e < NEDGES) atomicAdd(&g_deg[dst[e]], 1);
}

// single-block scan over 50000 degrees -> rowptr (exclusive), cursor, deg_inv
__global__ void scan_kernel() {
    __shared__ int sdata[1024];
    int tid = threadIdx.x;
    int carry = 0;
    for (int base = 0; base < NNODES; base += 1024) {
        int i = base + tid;
        int v = (i < NNODES) ? g_deg[i] : 0;
        __syncthreads();                 // protect sdata from previous iteration readers
        sdata[tid] = v;
        __syncthreads();
        #pragma unroll
        for (int off = 1; off < 1024; off <<= 1) {
            int t = (tid >= off) ? sdata[tid - off] : 0;
            __syncthreads();
            sdata[tid] += t;
            __syncthreads();
        }
        int incl = sdata[tid];
        int excl = incl - v;
        if (i < NNODES) {
            g_rowptr[i] = carry + excl;
            g_cursor[i] = carry + excl;
            g_deginv[i] = 1.0f / fmaxf((float)v, 1.0f);
        }
        carry += sdata[1023];            // everyone reads the block total identically
    }
    if (tid == 0) g_rowptr[NNODES] = carry;   // == NEDGES
}

__global__ void scatter_kernel(const int* __restrict__ src,
                               const int* __restrict__ dst,
                               const int* __restrict__ rel) {
    int e = blockIdx.x * blockDim.x + threadIdx.x;
    if (e < NEDGES) {
        int d = dst[e];
        int pos = atomicAdd(&g_cursor[d], 1);
        g_edges[pos] = (rel[e] << 16) | src[e];
    }
}

// ---------------- per-layer weight assembly: g_W[k][o], k in [0,2304) ----------------
// k < 2048: W[r,i,o] = sum_b coeffs[l,r,b] * bases[l,b,i,o]    (r=k>>8, i=k&255)
// k >=2048: self_loops[l, k-2048, o]
__global__ void wcat_kernel(const float* __restrict__ bases,
                            const float* __restrict__ coeffs,
                            const float* __restrict__ selfw,
                            int l) {
    int k = blockIdx.x;
    int o = threadIdx.x;
    if (k < 2048) {
        int r = k >> 8;
        int i = k & 255;
        const float* cf = coeffs + (l * NREL + r) * NBASES;
        const float* bs = bases + ((size_t)l * NBASES) * HID * HID + i * HID + o;
        float s = 0.f;
        #pragma unroll 6
        for (int b = 0; b < NBASES; b++)
            s += cf[b] * bs[(size_t)b * HID * HID];
        g_W[k * HID + o] = s;
    } else {
        g_W[k * HID + o] = selfw[(size_t)l * HID * HID + (k - 2048) * HID + o];
    }
}

// ---------------- aggregation: tmpx[n, r*256+c] = deginv[n]*sum x[src,c] ; [2048+c]=x[n,c]
__global__ void agg_kernel(const float* __restrict__ xin) {
    int n = blockIdx.x;
    int c = threadIdx.x;
    int s0 = g_rowptr[n];
    int s1 = g_rowptr[n + 1];
    float a0 = 0.f, a1 = 0.f, a2 = 0.f, a3 = 0.f, a4 = 0.f, a5 = 0.f, a6 = 0.f, a7 = 0.f;
    for (int j = s0; j < s1; j++) {
        int p = __ldg(&g_edges[j]);          // uniform across block
        int s = p & 0xFFFF;
        int r = p >> 16;
        float v = __ldg(&xin[(size_t)s * HID + c]);
        switch (r) {                         // r uniform -> no divergence, keeps acc in regs
            case 0: a0 += v; break;
            case 1: a1 += v; break;
            case 2: a2 += v; break;
            case 3: a3 += v; break;
            case 4: a4 += v; break;
            case 5: a5 += v; break;
            case 6: a6 += v; break;
            default: a7 += v; break;
        }
    }
    float dinv = g_deginv[n];
    float* out = g_tmpx + (size_t)n * KTOT;
    out[0 * HID + c] = a0 * dinv;
    out[1 * HID + c] = a1 * dinv;
    out[2 * HID + c] = a2 * dinv;
    out[3 * HID + c] = a3 * dinv;
    out[4 * HID + c] = a4 * dinv;
    out[5 * HID + c] = a5 * dinv;
    out[6 * HID + c] = a6 * dinv;
    out[7 * HID + c] = a7 * dinv;
    out[2048 + c] = xin[(size_t)n * HID + c];
}

// ---------------- fp32 SIMT GEMM: C[M,256] = tmpx[MPAD,2304] @ g_W[2304,256] (+relu) ----
#define BM 128
#define BN 128
#define BK 16
__global__ __launch_bounds__(256) void gemm_kernel(const float* __restrict__ A,
                                                   const float* __restrict__ B,
                                                   float* __restrict__ C,
                                                   int m_store, int do_relu) {
    __shared__ float As[BK][BM];   // transposed A tile
    __shared__ float Bs[BK][BN];
    const int K = KTOT;
    int brow = blockIdx.x * BM;
    int bcol = blockIdx.y * BN;
    int tid = threadIdx.x;
    int tr = tid >> 4;             // 0..15
    int tc = tid & 15;             // 0..15
    float acc[8][8];
    #pragma unroll
    for (int i = 0; i < 8; i++)
        #pragma unroll
        for (int j = 0; j < 8; j++) acc[i][j] = 0.f;

    for (int k0 = 0; k0 < K; k0 += BK) {
        // load A tile: 128 rows x 16 k  (512 float4s, 2 per thread), store transposed
        #pragma unroll
        for (int s = 0; s < 2; s++) {
            int idx = tid + s * 256;
            int r = idx >> 2;
            int kq = idx & 3;
            float4 v = *reinterpret_cast<const float4*>(&A[(size_t)(brow + r) * K + k0 + kq * 4]);
            As[kq * 4 + 0][r] = v.x;
            As[kq * 4 + 1][r] = v.y;
            As[kq * 4 + 2][r] = v.z;
            As[kq * 4 + 3][r] = v.w;
        }
        // load B tile: 16 rows x 128 cols (512 float4s, 2 per thread)
        #pragma unroll
        for (int s = 0; s < 2; s++) {
            int idx = tid + s * 256;
            int r = idx >> 5;            // 0..15
            int c4 = idx & 31;           // 0..31
            *reinterpret_cast<float4*>(&Bs[r][c4 * 4]) =
                *reinterpret_cast<const float4*>(&B[(size_t)(k0 + r) * HID + bcol + c4 * 4]);
        }
        __syncthreads();
        #pragma unroll
        for (int k = 0; k < BK; k++) {
            float ra[8], rb[8];
            *reinterpret_cast<float4*>(&ra[0]) = *reinterpret_cast<const float4*>(&As[k][tr * 8]);
            *reinterpret_cast<float4*>(&ra[4]) = *reinterpret_cast<const float4*>(&As[k][tr * 8 + 4]);
            *reinterpret_cast<float4*>(&rb[0]) = *reinterpret_cast<const float4*>(&Bs[k][tc * 8]);
            *reinterpret_cast<float4*>(&rb[4]) = *reinterpret_cast<const float4*>(&Bs[k][tc * 8 + 4]);
            #pragma unroll
            for (int i = 0; i < 8; i++)
                #pragma unroll
                for (int j = 0; j < 8; j++) acc[i][j] += ra[i] * rb[j];
        }
        __syncthreads();
    }
    // store
    #pragma unroll
    for (int i = 0; i < 8; i++) {
        int row = brow + tr * 8 + i;
        if (row < m_store) {
            float4 v0, v1;
            v0.x = acc[i][0]; v0.y = acc[i][1]; v0.z = acc[i][2]; v0.w = acc[i][3];
            v1.x = acc[i][4]; v1.y = acc[i][5]; v1.z = acc[i][6]; v1.w = acc[i][7];
            if (do_relu) {
                v0.x = fmaxf(v0.x, 0.f); v0.y = fmaxf(v0.y, 0.f);
                v0.z = fmaxf(v0.z, 0.f); v0.w = fmaxf(v0.w, 0.f);
                v1.x = fmaxf(v1.x, 0.f); v1.y = fmaxf(v1.y, 0.f);
                v1.z = fmaxf(v1.z, 0.f); v1.w = fmaxf(v1.w, 0.f);
            }
            *reinterpret_cast<float4*>(&C[(size_t)row * HID + bcol + tc * 8]) = v0;
            *reinterpret_cast<float4*>(&C[(size_t)row * HID + bcol + tc * 8 + 4]) = v1;
        }
    }
}

// ---------------- launch ----------------
extern "C" void kernel_launch(void* const* d_in, const int* in_sizes, int n_in,
                              void* d_out, int out_size) {
    // locate inputs by element count (all distinct)
    const int*   edge_index = nullptr;   // 1600000
    const int*   edge_type  = nullptr;   // 800000
    const float* emb        = nullptr;   // 12800000
    const float* bases      = nullptr;   // 3932160
    const float* coeffs     = nullptr;   // 480
    const float* selfw      = nullptr;   // 131072
    for (int i = 0; i < n_in; i++) {
        switch (in_sizes[i]) {
            case 2 * NEDGES:                 edge_index = (const int*)d_in[i]; break;
            case NEDGES:                     edge_type  = (const int*)d_in[i]; break;
            case NNODES * HID:               emb        = (const float*)d_in[i]; break;
            case 2 * NBASES * HID * HID:     bases      = (const float*)d_in[i]; break;
            case 2 * NREL * NBASES:          coeffs     = (const float*)d_in[i]; break;
            case 2 * HID * HID:              selfw      = (const float*)d_in[i]; break;
            default: break;                  // num_nodes scalar etc.
        }
    }
    const int* srcp = edge_index;
    const int* dstp = edge_index + NEDGES;
    float* outp = (float*)d_out;

    // one-time per launch: degree, CSR
    zero_deg_kernel<<<(NNODES + 255) / 256, 256>>>();
    hist_kernel<<<(NEDGES + 255) / 256, 256>>>(dstp);
    scan_kernel<<<1, 1024>>>();
    scatter_kernel<<<(NEDGES + 255) / 256, 256>>>(srcp, dstp, edge_type);

    float* g_x1_ptr = nullptr;
    cudaGetSymbolAddress((void**)&g_x1_ptr, g_x1);
    float* g_tmpx_ptr = nullptr;
    cudaGetSymbolAddress((void**)&g_tmpx_ptr, g_tmpx);
    float* g_W_ptr = nullptr;
    cudaGetSymbolAddress((void**)&g_W_ptr, g_W);

    dim3 ggrid(MPAD / BM, HID / BN);

    // layer 0: emb -> g_x1 (relu)
    wcat_kernel<<<KTOT, HID>>>(bases, coeffs, selfw, 0);
    agg_kernel<<<NNODES, HID>>>(emb);
    gemm_kernel<<<ggrid, 256>>>(g_tmpx_ptr, g_W_ptr, g_x1_ptr, NNODES, 1);

    // layer 1: g_x1 -> d_out (no relu)
    wcat_kernel<<<KTOT, HID>>>(bases, coeffs, selfw, 1);
    agg_kernel<<<NNODES, HID>>>(g_x1_ptr);
    gemm_kernel<<<ggrid, 256>>>(g_tmpx_ptr, g_W_ptr, outp, NNODES, 0);

    (void)out_size;
}

// round 3
// speedup vs baseline: 2.2465x; 2.2465x over previous
#include <cuda_runtime.h>
#include <cuda_bf16.h>
#include <cstdint>

// ---------------- problem constants ----------------
#define NNODES 50000
#define NEDGES 800000
#define NREL   8
#define HID    256
#define NBASES 30
#define KTOT   2304            // 8*256 relation cols + 256 self cols
#define MPAD   50176           // 392 * 128

// ---------------- device scratch (static, .bss zero-initialized) ----------------
__device__ int   g_deg[NNODES];
__device__ float g_deginv[NNODES];
__device__ int   g_rowptr[NNODES + 1];
__device__ int   g_cursor[NNODES];
__device__ int   g_edges[NEDGES];                    // packed (rel<<16)|src
__device__ __align__(256) __nv_bfloat16 g_Ahi[(size_t)MPAD * KTOT];  // pad rows stay 0
__device__ __align__(256) __nv_bfloat16 g_Alo[(size_t)MPAD * KTOT];
__device__ float g_W[KTOT * HID];                    // W[k][o] fp32
__device__ __align__(256) __nv_bfloat16 g_Bhi[HID * KTOT];  // W^T hi: [o][k]
__device__ __align__(256) __nv_bfloat16 g_Blo[HID * KTOT];  // W^T lo: [o][k]
__device__ float g_x1[(size_t)MPAD * HID];

// ================= helpers =================
__device__ __forceinline__ uint32_t smem_to_u32(const void* p) {
    uint32_t a;
    asm("{ .reg .u64 t; cvta.to.shared.u64 t, %1; cvt.u32.u64 %0, t; }" : "=r"(a) : "l"(p));
    return a;
}
#define SWZ128(off) ((off) ^ (((off) >> 3) & 0x70))

__device__ __forceinline__ void cp16(uint32_t dst, const void* src) {
    asm volatile("cp.async.cg.shared.global [%0], [%1], 16;" :: "r"(dst), "l"(src));
}
__device__ __forceinline__ void ldsm4(uint32_t& r0, uint32_t& r1, uint32_t& r2, uint32_t& r3,
                                      uint32_t addr) {
    asm volatile("ldmatrix.sync.aligned.m8n8.x4.shared.b16 {%0,%1,%2,%3}, [%4];"
                 : "=r"(r0), "=r"(r1), "=r"(r2), "=r"(r3) : "r"(addr));
}
__device__ __forceinline__ void mma16816(float* c, const uint32_t* a, const uint32_t* b) {
    asm volatile("mma.sync.aligned.m16n8k16.row.col.f32.bf16.bf16.f32 "
                 "{%0,%1,%2,%3}, {%4,%5,%6,%7}, {%8,%9}, {%0,%1,%2,%3};"
                 : "+f"(c[0]), "+f"(c[1]), "+f"(c[2]), "+f"(c[3])
                 : "r"(a[0]), "r"(a[1]), "r"(a[2]), "r"(a[3]), "r"(b[0]), "r"(b[1]));
}

// ---------------- setup kernels ----------------
__global__ void zero_deg_kernel() {
    int i = blockIdx.x * blockDim.x + threadIdx.x;
    if (i < NNODES) g_deg[i] = 0;
}
__global__ void hist_kernel(const int* __restrict__ dst) {
    int e = blockIdx.x * blockDim.x + threadIdx.x;
    if (e < NEDGES) atomicAdd(&g_deg[dst[e]], 1);
}
__global__ void scan_kernel() {
    __shared__ int sdata[1024];
    int tid = threadIdx.x;
    int carry = 0;
    for (int base = 0; base < NNODES; base += 1024) {
        int i = base + tid;
        int v = (i < NNODES) ? g_deg[i] : 0;
        __syncthreads();
        sdata[tid] = v;
        __syncthreads();
        #pragma unroll
        for (int off = 1; off < 1024; off <<= 1) {
            int t = (tid >= off) ? sdata[tid - off] : 0;
            __syncthreads();
            sdata[tid] += t;
            __syncthreads();
        }
        int incl = sdata[tid];
        int excl = incl - v;
        if (i < NNODES) {
            g_rowptr[i] = carry + excl;
            g_cursor[i] = carry + excl;
            g_deginv[i] = 1.0f / fmaxf((float)v, 1.0f);
        }
        carry += sdata[1023];
    }
    if (tid == 0) g_rowptr[NNODES] = carry;
}
__global__ void scatter_kernel(const int* __restrict__ src,
                               const int* __restrict__ dst,
                               const int* __restrict__ rel) {
    int e = blockIdx.x * blockDim.x + threadIdx.x;
    if (e < NEDGES) {
        int d = dst[e];
        int pos = atomicAdd(&g_cursor[d], 1);
        g_edges[pos] = (rel[e] << 16) | src[e];
    }
}

// ---------------- weight assembly: g_W[k][o] fp32 ----------------
__global__ void wcat_kernel(const float* __restrict__ bases,
                            const float* __restrict__ coeffs,
                            const float* __restrict__ selfw,
                            int l) {
    int k = blockIdx.x;
    int o = threadIdx.x;
    if (k < 2048) {
        int r = k >> 8;
        int i = k & 255;
        const float* cf = coeffs + (l * NREL + r) * NBASES;
        const float* bs = bases + ((size_t)l * NBASES) * HID * HID + i * HID + o;
        float s = 0.f;
        #pragma unroll 6
        for (int b = 0; b < NBASES; b++)
            s += cf[b] * bs[(size_t)b * HID * HID];
        g_W[k * HID + o] = s;
    } else {
        g_W[k * HID + o] = selfw[(size_t)l * HID * HID + (k - 2048) * HID + o];
    }
}

// transpose + bf16-split: g_Bhi/g_Blo [o][k] = split(g_W[k][o])
__global__ void wsplit_kernel() {
    __shared__ float t[32][33];
    int k0 = blockIdx.x * 32, o0 = blockIdx.y * 32;
    int tx = threadIdx.x, ty = threadIdx.y;
    t[ty][tx] = g_W[(k0 + ty) * HID + o0 + tx];
    __syncthreads();
    float v = t[tx][ty];                       // = W[k0+tx][o0+ty]
    __nv_bfloat16 h = __float2bfloat16(v);
    __nv_bfloat16 lo = __float2bfloat16(v - __bfloat162float(h));
    g_Bhi[(size_t)(o0 + ty) * KTOT + k0 + tx] = h;
    g_Blo[(size_t)(o0 + ty) * KTOT + k0 + tx] = lo;
}

// ---------------- aggregation -> bf16 hi/lo A rows ----------------
__global__ void agg_kernel(const float* __restrict__ xin) {
    int n = blockIdx.x;
    int c = threadIdx.x;
    int s0 = g_rowptr[n];
    int s1 = g_rowptr[n + 1];
    float a0=0.f,a1=0.f,a2=0.f,a3=0.f,a4=0.f,a5=0.f,a6=0.f,a7=0.f;
    for (int j = s0; j < s1; j++) {
        int p = __ldg(&g_edges[j]);
        int s = p & 0xFFFF;
        int r = p >> 16;
        float v = __ldg(&xin[(size_t)s * HID + c]);
        switch (r) {
            case 0: a0 += v; break; case 1: a1 += v; break;
            case 2: a2 += v; break; case 3: a3 += v; break;
            case 4: a4 += v; break; case 5: a5 += v; break;
            case 6: a6 += v; break; default: a7 += v; break;
        }
    }
    float dinv = g_deginv[n];
    size_t base = (size_t)n * KTOT;
    float vals[9] = { a0*dinv, a1*dinv, a2*dinv, a3*dinv, a4*dinv, a5*dinv, a6*dinv, a7*dinv,
                      xin[(size_t)n * HID + c] };
    #pragma unroll
    for (int r = 0; r < 9; r++) {
        float v = vals[r];
        __nv_bfloat16 h = __float2bfloat16(v);
        __nv_bfloat16 lo = __float2bfloat16(v - __bfloat162float(h));
        size_t off = base + (r < 8 ? r * HID : 2048) + c;
        g_Ahi[off] = h;
        g_Alo[off] = lo;
    }
}

// ---------------- HMMA GEMM: C[M,256] = (Ahi+Alo)@(Bhi+Blo)^T (3-term bf16) ----------------
// CTA 128x128, 8 warps (4 along M x 2 along N), warp tile 32x64.
#define KC 64
#define NCHUNK (KTOT / KC)     // 36
#define STAGE_BYTES (64 * 1024)
#define OFF_AH 0
#define OFF_AL (16 * 1024)
#define OFF_BH (32 * 1024)
#define OFF_BL (48 * 1024)
#define GEMM_SMEM (2 * STAGE_BYTES)

__device__ __forceinline__ void load_chunk(uint32_t sb, int brow, int bcol, int k0, int tid,
                                           const __nv_bfloat16* Ahi, const __nv_bfloat16* Alo,
                                           const __nv_bfloat16* Bhi, const __nv_bfloat16* Blo) {
    // each of 4 arrays: 128 rows x 64 bf16 = 1024 x 16B chunks; 4 chunks/thread/array
    #pragma unroll
    for (int q = 0; q < 4; q++) {
        int idx = tid + q * 256;
        int r = idx >> 3;                 // 0..127
        int c = idx & 7;                  // 16B chunk within 128B row
        uint32_t soff = SWZ128((uint32_t)(r * 128 + c * 16));
        const __nv_bfloat16* ga = Ahi + (size_t)(brow + r) * KTOT + k0 + c * 8;
        const __nv_bfloat16* gal = Alo + (size_t)(brow + r) * KTOT + k0 + c * 8;
        const __nv_bfloat16* gb = Bhi + (size_t)(bcol + r) * KTOT + k0 + c * 8;
        const __nv_bfloat16* gbl = Blo + (size_t)(bcol + r) * KTOT + k0 + c * 8;
        cp16(sb + OFF_AH + soff, ga);
        cp16(sb + OFF_AL + soff, gal);
        cp16(sb + OFF_BH + soff, gb);
        cp16(sb + OFF_BL + soff, gbl);
    }
}

__global__ __launch_bounds__(256) void mma_gemm_kernel(
    const __nv_bfloat16* __restrict__ Ahi, const __nv_bfloat16* __restrict__ Alo,
    const __nv_bfloat16* __restrict__ Bhi, const __nv_bfloat16* __restrict__ Blo,
    float* __restrict__ C, int m_store, int do_relu)
{
    extern __shared__ char smraw[];
    uint32_t smem_base = smem_to_u32(smraw);
    int tid = threadIdx.x;
    int wid = tid >> 5;
    int lane = tid & 31;
    int wm = wid & 3;              // warp row 0..3  -> rows wm*32..+32
    int wn = wid >> 2;             // warp col 0..1  -> cols wn*64..+64
    int brow = blockIdx.x * 128;
    int bcol = blockIdx.y * 128;

    float acc[2][8][4];
    #pragma unroll
    for (int i = 0; i < 2; i++)
        #pragma unroll
        for (int j = 0; j < 8; j++)
            #pragma unroll
            for (int q = 0; q < 4; q++) acc[i][j][q] = 0.f;

    // prologue
    load_chunk(smem_base, brow, bcol, 0, tid, Ahi, Alo, Bhi, Blo);
    asm volatile("cp.async.commit_group;" ::: "memory");
    load_chunk(smem_base + STAGE_BYTES, brow, bcol, KC, tid, Ahi, Alo, Bhi, Blo);
    asm volatile("cp.async.commit_group;" ::: "memory");

    // precomputed per-thread ldmatrix address pieces
    int a_row = wm * 32 + (lane & 15);          // + g*16
    int a_kc8 = (lane >> 4) << 3;               // 0 or 8
    int tg = lane >> 3;
    int b_nbase = wn * 64 + ((tg >> 1) << 3) + (lane & 7);   // + j*16
    int b_kc8 = (tg & 1) << 3;

    for (int i = 0; i < NCHUNK; i++) {
        uint32_t sb = smem_base + (uint32_t)(i & 1) * STAGE_BYTES;
        asm volatile("cp.async.wait_group 1;" ::: "memory");
        __syncthreads();

        #pragma unroll
        for (int ks = 0; ks < 4; ks++) {
            int k = ks * 16;
            #pragma unroll
            for (int p = 0; p < 3; p++) {
                uint32_t aoff = (p == 1) ? OFF_AL : OFF_AH;
                uint32_t boff = (p == 2) ? OFF_BL : OFF_BH;
                uint32_t a[2][4];
                #pragma unroll
                for (int g = 0; g < 2; g++) {
                    uint32_t byteoff = (uint32_t)((a_row + g * 16) * 128 + (k + a_kc8) * 2);
                    ldsm4(a[g][0], a[g][1], a[g][2], a[g][3], sb + aoff + SWZ128(byteoff));
                }
                uint32_t b[4][4];
                #pragma unroll
                for (int j = 0; j < 4; j++) {
                    uint32_t byteoff = (uint32_t)((b_nbase + j * 16) * 128 + (k + b_kc8) * 2);
                    ldsm4(b[j][0], b[j][1], b[j][2], b[j][3], sb + boff + SWZ128(byteoff));
                }
                #pragma unroll
                for (int mt = 0; mt < 2; mt++)
                    #pragma unroll
                    for (int nt = 0; nt < 8; nt++)
                        mma16816(acc[mt][nt], a[mt], &b[nt >> 1][(nt & 1) * 2]);
            }
        }
        __syncthreads();
        if (i + 2 < NCHUNK)
            load_chunk(sb, brow, bcol, (i + 2) * KC, tid, Ahi, Alo, Bhi, Blo);
        asm volatile("cp.async.commit_group;" ::: "memory");
    }

    // epilogue: write C
    int col = bcol + wn * 64 + 2 * (lane & 3);
    #pragma unroll
    for (int mt = 0; mt < 2; mt++) {
        int r0 = brow + wm * 32 + mt * 16 + (lane >> 2);
        int r1 = r0 + 8;
        #pragma unroll
        for (int nt = 0; nt < 8; nt++) {
            float2 v0 = make_float2(acc[mt][nt][0], acc[mt][nt][1]);
            float2 v1 = make_float2(acc[mt][nt][2], acc[mt][nt][3]);
            if (do_relu) {
                v0.x = fmaxf(v0.x, 0.f); v0.y = fmaxf(v0.y, 0.f);
                v1.x = fmaxf(v1.x, 0.f); v1.y = fmaxf(v1.y, 0.f);
            }
            if (r0 < m_store)
                *reinterpret_cast<float2*>(&C[(size_t)r0 * HID + col + nt * 8]) = v0;
            if (r1 < m_store)
                *reinterpret_cast<float2*>(&C[(size_t)r1 * HID + col + nt * 8]) = v1;
        }
    }
}

// ---------------- launch ----------------
extern "C" void kernel_launch(void* const* d_in, const int* in_sizes, int n_in,
                              void* d_out, int out_size) {
    const int*   edge_index = nullptr;
    const int*   edge_type  = nullptr;
    const float* emb        = nullptr;
    const float* bases      = nullptr;
    const float* coeffs     = nullptr;
    const float* selfw      = nullptr;
    for (int i = 0; i < n_in; i++) {
        switch (in_sizes[i]) {
            case 2 * NEDGES:             edge_index = (const int*)d_in[i]; break;
            case NEDGES:                 edge_type  = (const int*)d_in[i]; break;
            case NNODES * HID:           emb        = (const float*)d_in[i]; break;
            case 2 * NBASES * HID * HID: bases      = (const float*)d_in[i]; break;
            case 2 * NREL * NBASES:      coeffs     = (const float*)d_in[i]; break;
            case 2 * HID * HID:          selfw      = (const float*)d_in[i]; break;
            default: break;
        }
    }
    const int* srcp = edge_index;
    const int* dstp = edge_index + NEDGES;
    float* outp = (float*)d_out;

    zero_deg_kernel<<<(NNODES + 255) / 256, 256>>>();
    hist_kernel<<<(NEDGES + 255) / 256, 256>>>(dstp);
    scan_kernel<<<1, 1024>>>();
    scatter_kernel<<<(NEDGES + 255) / 256, 256>>>(srcp, dstp, edge_type);

    __nv_bfloat16 *ahi_p, *alo_p, *bhi_p, *blo_p;
    float* x1_p;
    cudaGetSymbolAddress((void**)&ahi_p, g_Ahi);
    cudaGetSymbolAddress((void**)&alo_p, g_Alo);
    cudaGetSymbolAddress((void**)&bhi_p, g_Bhi);
    cudaGetSymbolAddress((void**)&blo_p, g_Blo);
    cudaGetSymbolAddress((void**)&x1_p, g_x1);

    cudaFuncSetAttribute(mma_gemm_kernel, cudaFuncAttributeMaxDynamicSharedMemorySize, GEMM_SMEM);

    dim3 wsgrid(KTOT / 32, HID / 32);
    dim3 wsblk(32, 32);
    dim3 ggrid(MPAD / 128, HID / 128);

    // layer 0: emb -> g_x1 (relu)
    wcat_kernel<<<KTOT, HID>>>(bases, coeffs, selfw, 0);
    wsplit_kernel<<<wsgrid, wsblk>>>();
    agg_kernel<<<NNODES, HID>>>(emb);
    mma_gemm_kernel<<<ggrid, 256, GEMM_SMEM>>>(ahi_p, alo_p, bhi_p, blo_p, x1_p, NNODES, 1);

    // layer 1: g_x1 -> d_out (no relu)
    wcat_kernel<<<KTOT, HID>>>(bases, coeffs, selfw, 1);
    wsplit_kernel<<<wsgrid, wsblk>>>();
    agg_kernel<<<NNODES, HID>>>(x1_p);
    mma_gemm_kernel<<<ggrid, 256, GEMM_SMEM>>>(ahi_p, alo_p, bhi_p, blo_p, outp, NNODES, 0);

    (void)out_size;
}

// round 4
// speedup vs baseline: 2.2908x; 1.0197x over previous
#include <cuda_runtime.h>
#include <cuda_bf16.h>
#include <cstdint>

// ---------------- problem constants ----------------
#define NNODES 50000
#define NEDGES 800000
#define NREL   8
#define HID    256
#define NBASES 30
#define KTOT   2304            // 8*256 relation cols + 256 self cols
#define MPAD   50176           // array padding; GEMM uses 391*128 = 50048 rows

// ---------------- device scratch (static, .bss zero-initialized) ----------------
__device__ int   g_deg[NNODES];
__device__ float g_deginv[NNODES];
__device__ int   g_rowptr[NNODES + 1];
__device__ int   g_cursor[NNODES];
__device__ int   g_edges[NEDGES];                    // packed (rel<<16)|src
__device__ __align__(256) __nv_bfloat16 g_Ahi[(size_t)MPAD * KTOT];  // pad rows stay 0
__device__ __align__(256) __nv_bfloat16 g_Alo[(size_t)MPAD * KTOT];
__device__ float g_W[KTOT * HID];                    // W[k][o] fp32
__device__ __align__(256) __nv_bfloat16 g_Bhi[HID * KTOT];  // W^T hi: [o][k]
__device__ __align__(256) __nv_bfloat16 g_Blo[HID * KTOT];  // W^T lo: [o][k]
__device__ float g_x1[(size_t)MPAD * HID];

// ================= helpers =================
__device__ __forceinline__ uint32_t smem_to_u32(const void* p) {
    uint32_t a;
    asm("{ .reg .u64 t; cvta.to.shared.u64 t, %1; cvt.u32.u64 %0, t; }" : "=r"(a) : "l"(p));
    return a;
}
#define SWZ128(off) ((off) ^ (((off) >> 3) & 0x70))

__device__ __forceinline__ void cp16(uint32_t dst, const void* src) {
    asm volatile("cp.async.cg.shared.global [%0], [%1], 16;" :: "r"(dst), "l"(src));
}
__device__ __forceinline__ void ldsm4(uint32_t& r0, uint32_t& r1, uint32_t& r2, uint32_t& r3,
                                      uint32_t addr) {
    asm volatile("ldmatrix.sync.aligned.m8n8.x4.shared.b16 {%0,%1,%2,%3}, [%4];"
                 : "=r"(r0), "=r"(r1), "=r"(r2), "=r"(r3) : "r"(addr));
}
__device__ __forceinline__ void mma16816(float* c, const uint32_t* a, const uint32_t* b) {
    asm volatile("mma.sync.aligned.m16n8k16.row.col.f32.bf16.bf16.f32 "
                 "{%0,%1,%2,%3}, {%4,%5,%6,%7}, {%8,%9}, {%0,%1,%2,%3};"
                 : "+f"(c[0]), "+f"(c[1]), "+f"(c[2]), "+f"(c[3])
                 : "r"(a[0]), "r"(a[1]), "r"(a[2]), "r"(a[3]), "r"(b[0]), "r"(b[1]));
}

// ---------------- setup kernels ----------------
__global__ void zero_deg_kernel() {
    int i = blockIdx.x * blockDim.x + threadIdx.x;
    if (i < NNODES) g_deg[i] = 0;
}
__global__ void hist_kernel(const int* __restrict__ dst) {
    int e = blockIdx.x * blockDim.x + threadIdx.x;
    if (e < NEDGES) atomicAdd(&g_deg[dst[e]], 1);
}
__global__ void scan_kernel() {
    __shared__ int sdata[1024];
    int tid = threadIdx.x;
    int carry = 0;
    for (int base = 0; base < NNODES; base += 1024) {
        int i = base + tid;
        int v = (i < NNODES) ? g_deg[i] : 0;
        __syncthreads();
        sdata[tid] = v;
        __syncthreads();
        #pragma unroll
        for (int off = 1; off < 1024; off <<= 1) {
            int t = (tid >= off) ? sdata[tid - off] : 0;
            __syncthreads();
            sdata[tid] += t;
            __syncthreads();
        }
        int incl = sdata[tid];
        int excl = incl - v;
        if (i < NNODES) {
            g_rowptr[i] = carry + excl;
            g_cursor[i] = carry + excl;
            g_deginv[i] = 1.0f / fmaxf((float)v, 1.0f);
        }
        carry += sdata[1023];
    }
    if (tid == 0) g_rowptr[NNODES] = carry;
}
__global__ void scatter_kernel(const int* __restrict__ src,
                               const int* __restrict__ dst,
                               const int* __restrict__ rel) {
    int e = blockIdx.x * blockDim.x + threadIdx.x;
    if (e < NEDGES) {
        int d = dst[e];
        int pos = atomicAdd(&g_cursor[d], 1);
        g_edges[pos] = (rel[e] << 16) | src[e];
    }
}

// ---------------- weight assembly: g_W[k][o] fp32 ----------------
__global__ void wcat_kernel(const float* __restrict__ bases,
                            const float* __restrict__ coeffs,
                            const float* __restrict__ selfw,
                            int l) {
    int k = blockIdx.x;
    int o = threadIdx.x;
    if (k < 2048) {
        int r = k >> 8;
        int i = k & 255;
        const float* cf = coeffs + (l * NREL + r) * NBASES;
        const float* bs = bases + ((size_t)l * NBASES) * HID * HID + i * HID + o;
        float s = 0.f;
        #pragma unroll 6
        for (int b = 0; b < NBASES; b++)
            s += cf[b] * bs[(size_t)b * HID * HID];
        g_W[k * HID + o] = s;
    } else {
        g_W[k * HID + o] = selfw[(size_t)l * HID * HID + (k - 2048) * HID + o];
    }
}

// transpose + bf16-split: g_Bhi/g_Blo [o][k] = split(g_W[k][o])
__global__ void wsplit_kernel() {
    __shared__ float t[32][33];
    int k0 = blockIdx.x * 32, o0 = blockIdx.y * 32;
    int tx = threadIdx.x, ty = threadIdx.y;
    t[ty][tx] = g_W[(k0 + ty) * HID + o0 + tx];
    __syncthreads();
    float v = t[tx][ty];                       // = W[k0+tx][o0+ty]
    __nv_bfloat16 h = __float2bfloat16(v);
    __nv_bfloat16 lo = __float2bfloat16(v - __bfloat162float(h));
    g_Bhi[(size_t)(o0 + ty) * KTOT + k0 + tx] = h;
    g_Blo[(size_t)(o0 + ty) * KTOT + k0 + tx] = lo;
}

// ---------------- aggregation -> bf16 hi/lo A rows ----------------
__global__ void agg_kernel(const float* __restrict__ xin) {
    int n = blockIdx.x;
    int c = threadIdx.x;
    int s0 = g_rowptr[n];
    int s1 = g_rowptr[n + 1];
    float a0=0.f,a1=0.f,a2=0.f,a3=0.f,a4=0.f,a5=0.f,a6=0.f,a7=0.f;
    for (int j = s0; j < s1; j++) {
        int p = __ldg(&g_edges[j]);
        int s = p & 0xFFFF;
        int r = p >> 16;
        float v = __ldg(&xin[(size_t)s * HID + c]);
        switch (r) {
            case 0: a0 += v; break; case 1: a1 += v; break;
            case 2: a2 += v; break; case 3: a3 += v; break;
            case 4: a4 += v; break; case 5: a5 += v; break;
            case 6: a6 += v; break; default: a7 += v; break;
        }
    }
    float dinv = g_deginv[n];
    size_t base = (size_t)n * KTOT;
    float vals[9] = { a0*dinv, a1*dinv, a2*dinv, a3*dinv, a4*dinv, a5*dinv, a6*dinv, a7*dinv,
                      xin[(size_t)n * HID + c] };
    #pragma unroll
    for (int r = 0; r < 9; r++) {
        float v = vals[r];
        __nv_bfloat16 h = __float2bfloat16(v);
        __nv_bfloat16 lo = __float2bfloat16(v - __bfloat162float(h));
        size_t off = base + (r < 8 ? r * HID : 2048) + c;
        g_Ahi[off] = h;
        g_Alo[off] = lo;
    }
}

// ---------------- HMMA GEMM: C[M,256] = (Ahi+Alo)@(Bhi+Blo)^T (3-term bf16) ----------------
// CTA 128x256, 512 threads = 16 warps (4 M x 4 N), warp tile 32x64. Full N per CTA.
#define KC 64
#define NCHUNK (KTOT / KC)     // 36
#define ST_AH 0
#define ST_AL (16 * 1024)
#define ST_BH (32 * 1024)
#define ST_BL (64 * 1024)
#define STAGE_BYTES (96 * 1024)
#define GEMM_SMEM (2 * STAGE_BYTES)

__device__ __forceinline__ void load_chunk512(uint32_t sb, int brow, int k0, int tid,
                                              const __nv_bfloat16* Ahi, const __nv_bfloat16* Alo,
                                              const __nv_bfloat16* Bhi, const __nv_bfloat16* Blo) {
    // A: 128 rows x 8 chunks x {hi,lo} = 2048; B: 256 rows x 8 x {hi,lo} = 4096; 12/thread
    #pragma unroll
    for (int it = 0; it < 12; it++) {
        int u = tid + it * 512;
        if (u < 2048) {
            int idx = u & 1023;
            int r = idx >> 3, c = idx & 7;
            uint32_t so = SWZ128((uint32_t)(r * 128 + c * 16));
            const __nv_bfloat16* g = (u < 1024 ? Ahi : Alo) + (size_t)(brow + r) * KTOT + k0 + c * 8;
            cp16(sb + (u < 1024 ? ST_AH : ST_AL) + so, g);
        } else {
            int v = u - 2048;
            int idx = v & 2047;
            int r = idx >> 3, c = idx & 7;
            uint32_t so = SWZ128((uint32_t)(r * 128 + c * 16));
            const __nv_bfloat16* g = (v < 2048 ? Bhi : Blo) + (size_t)r * KTOT + k0 + c * 8;
            cp16(sb + (v < 2048 ? ST_BH : ST_BL) + so, g);
        }
    }
}

__global__ __launch_bounds__(512, 1) void mma_gemm_kernel(
    const __nv_bfloat16* __restrict__ Ahi, const __nv_bfloat16* __restrict__ Alo,
    const __nv_bfloat16* __restrict__ Bhi, const __nv_bfloat16* __restrict__ Blo,
    float* __restrict__ C, int m_store, int do_relu)
{
    extern __shared__ char smraw[];
    uint32_t smem_base = smem_to_u32(smraw);
    int tid = threadIdx.x;
    int wid = tid >> 5;
    int lane = tid & 31;
    int wm = wid & 3;              // warp row 0..3  -> rows wm*32
    int wn = wid >> 2;             // warp col 0..3  -> cols wn*64
    int brow = blockIdx.x * 128;

    float acc[2][8][4];
    #pragma unroll
    for (int i = 0; i < 2; i++)
        #pragma unroll
        for (int j = 0; j < 8; j++)
            #pragma unroll
            for (int q = 0; q < 4; q++) acc[i][j][q] = 0.f;

    // prologue
    load_chunk512(smem_base, brow, 0, tid, Ahi, Alo, Bhi, Blo);
    asm volatile("cp.async.commit_group;" ::: "memory");
    load_chunk512(smem_base + STAGE_BYTES, brow, KC, tid, Ahi, Alo, Bhi, Blo);
    asm volatile("cp.async.commit_group;" ::: "memory");

    // per-thread ldmatrix address pieces
    int a_row = wm * 32 + (lane & 15);          // + g*16
    int a_kc8 = (lane >> 4) << 3;               // 0 or 8
    int tg = lane >> 3;
    int b_nbase = wn * 64 + ((tg >> 1) << 3) + (lane & 7);   // + j*16
    int b_kc8 = (tg & 1) << 3;

    for (int i = 0; i < NCHUNK; i++) {
        uint32_t sb = smem_base + (uint32_t)(i & 1) * STAGE_BYTES;
        asm volatile("cp.async.wait_group 1;" ::: "memory");
        __syncthreads();

        #pragma unroll
        for (int ks = 0; ks < 4; ks++) {
            int k = ks * 16;
            // fragments (cached across the 3 passes)
            uint32_t ah[2][4], al[2][4], bh[4][4], bl[4][4];
            #pragma unroll
            for (int g = 0; g < 2; g++) {
                uint32_t bo = (uint32_t)((a_row + g * 16) * 128 + (k + a_kc8) * 2);
                ldsm4(ah[g][0], ah[g][1], ah[g][2], ah[g][3], sb + ST_AH + SWZ128(bo));
            }
            #pragma unroll
            for (int j = 0; j < 4; j++) {
                uint32_t bo = (uint32_t)((b_nbase + j * 16) * 128 + (k + b_kc8) * 2);
                ldsm4(bh[j][0], bh[j][1], bh[j][2], bh[j][3], sb + ST_BH + SWZ128(bo));
            }
            // pass 0: AH x BH
            #pragma unroll
            for (int mt = 0; mt < 2; mt++)
                #pragma unroll
                for (int nt = 0; nt < 8; nt++)
                    mma16816(acc[mt][nt], ah[mt], &bh[nt >> 1][(nt & 1) * 2]);
            // pass 1: AL x BH
            #pragma unroll
            for (int g = 0; g < 2; g++) {
                uint32_t bo = (uint32_t)((a_row + g * 16) * 128 + (k + a_kc8) * 2);
                ldsm4(al[g][0], al[g][1], al[g][2], al[g][3], sb + ST_AL + SWZ128(bo));
            }
            #pragma unroll
            for (int mt = 0; mt < 2; mt++)
                #pragma unroll
                for (int nt = 0; nt < 8; nt++)
                    mma16816(acc[mt][nt], al[mt], &bh[nt >> 1][(nt & 1) * 2]);
            // pass 2: AH x BL
            #pragma unroll
            for (int j = 0; j < 4; j++) {
                uint32_t bo = (uint32_t)((b_nbase + j * 16) * 128 + (k + b_kc8) * 2);
                ldsm4(bl[j][0], bl[j][1], bl[j][2], bl[j][3], sb + ST_BL + SWZ128(bo));
            }
            #pragma unroll
            for (int mt = 0; mt < 2; mt++)
                #pragma unroll
                for (int nt = 0; nt < 8; nt++)
                    mma16816(acc[mt][nt], ah[mt], &bl[nt >> 1][(nt & 1) * 2]);
        }
        __syncthreads();
        if (i + 2 < NCHUNK)
            load_chunk512(sb, brow, (i + 2) * KC, tid, Ahi, Alo, Bhi, Blo);
        asm volatile("cp.async.commit_group;" ::: "memory");
    }

    // epilogue: write C
    int col = wn * 64 + 2 * (lane & 3);
    #pragma unroll
    for (int mt = 0; mt < 2; mt++) {
        int r0 = brow + wm * 32 + mt * 16 + (lane >> 2);
        int r1 = r0 + 8;
        #pragma unroll
        for (int nt = 0; nt < 8; nt++) {
            float2 v0 = make_float2(acc[mt][nt][0], acc[mt][nt][1]);
            float2 v1 = make_float2(acc[mt][nt][2], acc[mt][nt][3]);
            if (do_relu) {
                v0.x = fmaxf(v0.x, 0.f); v0.y = fmaxf(v0.y, 0.f);
                v1.x = fmaxf(v1.x, 0.f); v1.y = fmaxf(v1.y, 0.f);
            }
            if (r0 < m_store)
                *reinterpret_cast<float2*>(&C[(size_t)r0 * HID + col + nt * 8]) = v0;
            if (r1 < m_store)
                *reinterpret_cast<float2*>(&C[(size_t)r1 * HID + col + nt * 8]) = v1;
        }
    }
}

// ---------------- launch ----------------
extern "C" void kernel_launch(void* const* d_in, const int* in_sizes, int n_in,
                              void* d_out, int out_size) {
    const int*   edge_index = nullptr;
    const int*   edge_type  = nullptr;
    const float* emb        = nullptr;
    const float* bases      = nullptr;
    const float* coeffs     = nullptr;
    const float* selfw      = nullptr;
    for (int i = 0; i < n_in; i++) {
        switch (in_sizes[i]) {
            case 2 * NEDGES:             edge_index = (const int*)d_in[i]; break;
            case NEDGES:                 edge_type  = (const int*)d_in[i]; break;
            case NNODES * HID:           emb        = (const float*)d_in[i]; break;
            case 2 * NBASES * HID * HID: bases      = (const float*)d_in[i]; break;
            case 2 * NREL * NBASES:      coeffs     = (const float*)d_in[i]; break;
            case 2 * HID * HID:          selfw      = (const float*)d_in[i]; break;
            default: break;
        }
    }
    const int* srcp = edge_index;
    const int* dstp = edge_index + NEDGES;
    float* outp = (float*)d_out;

    zero_deg_kernel<<<(NNODES + 255) / 256, 256>>>();
    hist_kernel<<<(NEDGES + 255) / 256, 256>>>(dstp);
    scan_kernel<<<1, 1024>>>();
    scatter_kernel<<<(NEDGES + 255) / 256, 256>>>(srcp, dstp, edge_type);

    __nv_bfloat16 *ahi_p, *alo_p, *bhi_p, *blo_p;
    float* x1_p;
    cudaGetSymbolAddress((void**)&ahi_p, g_Ahi);
    cudaGetSymbolAddress((void**)&alo_p, g_Alo);
    cudaGetSymbolAddress((void**)&bhi_p, g_Bhi);
    cudaGetSymbolAddress((void**)&blo_p, g_Blo);
    cudaGetSymbolAddress((void**)&x1_p, g_x1);

    cudaFuncSetAttribute(mma_gemm_kernel, cudaFuncAttributeMaxDynamicSharedMemorySize, GEMM_SMEM);

    dim3 wsgrid(KTOT / 32, HID / 32);
    dim3 wsblk(32, 32);
    int ggrid = 391;                      // 391*128 = 50048 >= 50000 (pad rows are zero)

    // layer 0: emb -> g_x1 (relu)
    wcat_kernel<<<KTOT, HID>>>(bases, coeffs, selfw, 0);
    wsplit_kernel<<<wsgrid, wsblk>>>();
    agg_kernel<<<NNODES, HID>>>(emb);
    mma_gemm_kernel<<<ggrid, 512, GEMM_SMEM>>>(ahi_p, alo_p, bhi_p, blo_p, x1_p, NNODES, 1);

    // layer 1: g_x1 -> d_out (no relu)
    wcat_kernel<<<KTOT, HID>>>(bases, coeffs, selfw, 1);
    wsplit_kernel<<<wsgrid, wsblk>>>();
    agg_kernel<<<NNODES, HID>>>(x1_p);
    mma_gemm_kernel<<<ggrid, 512, GEMM_SMEM>>>(ahi_p, alo_p, bhi_p, blo_p, outp, NNODES, 0);

    (void)out_size;
}

// round 5
// speedup vs baseline: 2.3768x; 1.0375x over previous
#include <cuda_runtime.h>
#include <cuda_bf16.h>
#include <cstdint>

// ---------------- problem constants ----------------
#define NNODES 50000
#define NEDGES 800000
#define NREL   8
#define HID    256
#define NBASES 30
#define KTOT   2304            // 8*256 relation cols + 256 self cols
#define MPAD   50176           // array padding; GEMM uses 391*128 = 50048 rows

// ---------------- device scratch (static, .bss zero-initialized) ----------------
__device__ int   g_deg[NNODES];
__device__ float g_deginv[NNODES];
__device__ int   g_rowptr[NNODES + 1];
__device__ int   g_cursor[NNODES];
__device__ int   g_edges[NEDGES];                    // packed (rel<<16)|src
__device__ __align__(256) __nv_bfloat16 g_Ahi[(size_t)MPAD * KTOT];  // pad rows stay 0
__device__ __align__(256) __nv_bfloat16 g_Alo[(size_t)MPAD * KTOT];
__device__ float g_W[KTOT * HID];                    // W[k][o] fp32 (reused serially on s1)
__device__ __align__(256) __nv_bfloat16 g_Bhi[2][HID * KTOT];  // per-layer W^T hi: [o][k]
__device__ __align__(256) __nv_bfloat16 g_Blo[2][HID * KTOT];  // per-layer W^T lo: [o][k]
__device__ float g_x1[(size_t)MPAD * HID];

// ================= helpers =================
__device__ __forceinline__ uint32_t smem_to_u32(const void* p) {
    uint32_t a;
    asm("{ .reg .u64 t; cvta.to.shared.u64 t, %1; cvt.u32.u64 %0, t; }" : "=r"(a) : "l"(p));
    return a;
}
#define SWZ128(off) ((off) ^ (((off) >> 3) & 0x70))

__device__ __forceinline__ void cp16(uint32_t dst, const void* src) {
    asm volatile("cp.async.cg.shared.global [%0], [%1], 16;" :: "r"(dst), "l"(src));
}
__device__ __forceinline__ void ldsm4(uint32_t& r0, uint32_t& r1, uint32_t& r2, uint32_t& r3,
                                      uint32_t addr) {
    asm volatile("ldmatrix.sync.aligned.m8n8.x4.shared.b16 {%0,%1,%2,%3}, [%4];"
                 : "=r"(r0), "=r"(r1), "=r"(r2), "=r"(r3) : "r"(addr));
}
__device__ __forceinline__ void mma16816(float* c, const uint32_t* a, const uint32_t* b) {
    asm volatile("mma.sync.aligned.m16n8k16.row.col.f32.bf16.bf16.f32 "
                 "{%0,%1,%2,%3}, {%4,%5,%6,%7}, {%8,%9}, {%0,%1,%2,%3};"
                 : "+f"(c[0]), "+f"(c[1]), "+f"(c[2]), "+f"(c[3])
                 : "r"(a[0]), "r"(a[1]), "r"(a[2]), "r"(a[3]), "r"(b[0]), "r"(b[1]));
}

// ---------------- setup kernels ----------------
__global__ void hist_kernel(const int* __restrict__ dst) {
    int e = blockIdx.x * blockDim.x + threadIdx.x;
    if (e < NEDGES) atomicAdd(&g_deg[dst[e]], 1);
}

// single-block shuffle scan over 50000 degrees -> rowptr/cursor/deg_inv
__global__ void scan_kernel() {
    __shared__ int wsum[32];
    int tid = threadIdx.x;
    int lane = tid & 31;
    int wid = tid >> 5;
    int carry = 0;
    for (int base = 0; base < NNODES; base += 1024) {
        int i = base + tid;
        int v = (i < NNODES) ? g_deg[i] : 0;
        // warp inclusive scan
        int x = v;
        #pragma unroll
        for (int off = 1; off < 32; off <<= 1) {
            int t = __shfl_up_sync(0xFFFFFFFF, x, off);
            if (lane >= off) x += t;
        }
        if (lane == 31) wsum[wid] = x;
        __syncthreads();
        if (wid == 0) {
            int s = wsum[lane];
            #pragma unroll
            for (int off = 1; off < 32; off <<= 1) {
                int t = __shfl_up_sync(0xFFFFFFFF, s, off);
                if (lane >= off) s += t;
            }
            wsum[lane] = s;
        }
        __syncthreads();
        int excl = x - v + (wid > 0 ? wsum[wid - 1] : 0);
        int total = wsum[31];
        if (i < NNODES) {
            g_rowptr[i] = carry + excl;
            g_cursor[i] = carry + excl;
            g_deginv[i] = 1.0f / fmaxf((float)v, 1.0f);
        }
        carry += total;
        __syncthreads();     // protect wsum before next iteration
    }
    if (tid == 0) g_rowptr[NNODES] = carry;
}

__global__ void scatter_kernel(const int* __restrict__ src,
                               const int* __restrict__ dst,
                               const int* __restrict__ rel) {
    int e = blockIdx.x * blockDim.x + threadIdx.x;
    if (e < NEDGES) {
        int d = dst[e];
        int pos = atomicAdd(&g_cursor[d], 1);
        g_edges[pos] = (rel[e] << 16) | src[e];
    }
}

// ---------------- weight assembly: g_W[k][o] fp32 ----------------
__global__ void wcat_kernel(const float* __restrict__ bases,
                            const float* __restrict__ coeffs,
                            const float* __restrict__ selfw,
                            int l) {
    int k = blockIdx.x;
    int o = threadIdx.x;
    if (k < 2048) {
        int r = k >> 8;
        int i = k & 255;
        const float* cf = coeffs + (l * NREL + r) * NBASES;
        const float* bs = bases + ((size_t)l * NBASES) * HID * HID + i * HID + o;
        float s = 0.f;
        #pragma unroll 6
        for (int b = 0; b < NBASES; b++)
            s += cf[b] * bs[(size_t)b * HID * HID];
        g_W[k * HID + o] = s;
    } else {
        g_W[k * HID + o] = selfw[(size_t)l * HID * HID + (k - 2048) * HID + o];
    }
}

// transpose + bf16-split into per-layer buffers
__global__ void wsplit_kernel(int l) {
    __shared__ float t[32][33];
    int k0 = blockIdx.x * 32, o0 = blockIdx.y * 32;
    int tx = threadIdx.x, ty = threadIdx.y;
    t[ty][tx] = g_W[(k0 + ty) * HID + o0 + tx];
    __syncthreads();
    float v = t[tx][ty];                       // = W[k0+tx][o0+ty]
    __nv_bfloat16 h = __float2bfloat16(v);
    __nv_bfloat16 lo = __float2bfloat16(v - __bfloat162float(h));
    g_Bhi[l][(size_t)(o0 + ty) * KTOT + k0 + tx] = h;
    g_Blo[l][(size_t)(o0 + ty) * KTOT + k0 + tx] = lo;
}

// ---------------- aggregation -> bf16 hi/lo A rows ----------------
__global__ void agg_kernel(const float* __restrict__ xin) {
    int n = blockIdx.x;
    int c = threadIdx.x;
    int s0 = g_rowptr[n];
    int s1 = g_rowptr[n + 1];
    float a0=0.f,a1=0.f,a2=0.f,a3=0.f,a4=0.f,a5=0.f,a6=0.f,a7=0.f;
    for (int j = s0; j < s1; j++) {
        int p = __ldg(&g_edges[j]);
        int s = p & 0xFFFF;
        int r = p >> 16;
        float v = __ldg(&xin[(size_t)s * HID + c]);
        switch (r) {
            case 0: a0 += v; break; case 1: a1 += v; break;
            case 2: a2 += v; break; case 3: a3 += v; break;
            case 4: a4 += v; break; case 5: a5 += v; break;
            case 6: a6 += v; break; default: a7 += v; break;
        }
    }
    float dinv = g_deginv[n];
    size_t base = (size_t)n * KTOT;
    float vals[9] = { a0*dinv, a1*dinv, a2*dinv, a3*dinv, a4*dinv, a5*dinv, a6*dinv, a7*dinv,
                      xin[(size_t)n * HID + c] };
    #pragma unroll
    for (int r = 0; r < 9; r++) {
        float v = vals[r];
        __nv_bfloat16 h = __float2bfloat16(v);
        __nv_bfloat16 lo = __float2bfloat16(v - __bfloat162float(h));
        size_t off = base + (r < 8 ? r * HID : 2048) + c;
        g_Ahi[off] = h;
        g_Alo[off] = lo;
    }
}

// ---------------- HMMA GEMM: C[M,256] = (Ahi+Alo)@(Bhi+Blo)^T (3-term bf16) ----------------
// CTA 128x256, 512 threads = 16 warps (4 M x 4 N), warp tile 32x64. Full N per CTA.
#define KC 64
#define NCHUNK (KTOT / KC)     // 36
#define ST_AH 0
#define ST_AL (16 * 1024)
#define ST_BH (32 * 1024)
#define ST_BL (64 * 1024)
#define STAGE_BYTES (96 * 1024)
#define GEMM_SMEM (2 * STAGE_BYTES)

__device__ __forceinline__ void load_chunk512(uint32_t sb, int brow, int k0, int tid,
                                              const __nv_bfloat16* Ahi, const __nv_bfloat16* Alo,
                                              const __nv_bfloat16* Bhi, const __nv_bfloat16* Blo) {
    #pragma unroll
    for (int it = 0; it < 12; it++) {
        int u = tid + it * 512;
        if (u < 2048) {
            int idx = u & 1023;
            int r = idx >> 3, c = idx & 7;
            uint32_t so = SWZ128((uint32_t)(r * 128 + c * 16));
            const __nv_bfloat16* g = (u < 1024 ? Ahi : Alo) + (size_t)(brow + r) * KTOT + k0 + c * 8;
            cp16(sb + (u < 1024 ? ST_AH : ST_AL) + so, g);
        } else {
            int v = u - 2048;
            int idx = v & 2047;
            int r = idx >> 3, c = idx & 7;
            uint32_t so = SWZ128((uint32_t)(r * 128 + c * 16));
            const __nv_bfloat16* g = (v < 2048 ? Bhi : Blo) + (size_t)r * KTOT + k0 + c * 8;
            cp16(sb + (v < 2048 ? ST_BH : ST_BL) + so, g);
        }
    }
}

__global__ __launch_bounds__(512, 1) void mma_gemm_kernel(
    const __nv_bfloat16* __restrict__ Ahi, const __nv_bfloat16* __restrict__ Alo,
    const __nv_bfloat16* __restrict__ Bhi, const __nv_bfloat16* __restrict__ Blo,
    float* __restrict__ C, int m_store, int do_relu)
{
    extern __shared__ char smraw[];
    uint32_t smem_base = smem_to_u32(smraw);
    int tid = threadIdx.x;
    int wid = tid >> 5;
    int lane = tid & 31;
    int wm = wid & 3;
    int wn = wid >> 2;
    int brow = blockIdx.x * 128;

    float acc[2][8][4];
    #pragma unroll
    for (int i = 0; i < 2; i++)
        #pragma unroll
        for (int j = 0; j < 8; j++)
            #pragma unroll
            for (int q = 0; q < 4; q++) acc[i][j][q] = 0.f;

    load_chunk512(smem_base, brow, 0, tid, Ahi, Alo, Bhi, Blo);
    asm volatile("cp.async.commit_group;" ::: "memory");
    load_chunk512(smem_base + STAGE_BYTES, brow, KC, tid, Ahi, Alo, Bhi, Blo);
    asm volatile("cp.async.commit_group;" ::: "memory");

    int a_row = wm * 32 + (lane & 15);
    int a_kc8 = (lane >> 4) << 3;
    int tg = lane >> 3;
    int b_nbase = wn * 64 + ((tg >> 1) << 3) + (lane & 7);
    int b_kc8 = (tg & 1) << 3;

    for (int i = 0; i < NCHUNK; i++) {
        uint32_t sb = smem_base + (uint32_t)(i & 1) * STAGE_BYTES;
        asm volatile("cp.async.wait_group 1;" ::: "memory");
        __syncthreads();

        #pragma unroll
        for (int ks = 0; ks < 4; ks++) {
            int k = ks * 16;
            uint32_t ah[2][4], al[2][4], bh[4][4], bl[4][4];
            #pragma unroll
            for (int g = 0; g < 2; g++) {
                uint32_t bo = (uint32_t)((a_row + g * 16) * 128 + (k + a_kc8) * 2);
                ldsm4(ah[g][0], ah[g][1], ah[g][2], ah[g][3], sb + ST_AH + SWZ128(bo));
            }
            #pragma unroll
            for (int j = 0; j < 4; j++) {
                uint32_t bo = (uint32_t)((b_nbase + j * 16) * 128 + (k + b_kc8) * 2);
                ldsm4(bh[j][0], bh[j][1], bh[j][2], bh[j][3], sb + ST_BH + SWZ128(bo));
            }
            #pragma unroll
            for (int mt = 0; mt < 2; mt++)
                #pragma unroll
                for (int nt = 0; nt < 8; nt++)
                    mma16816(acc[mt][nt], ah[mt], &bh[nt >> 1][(nt & 1) * 2]);
            #pragma unroll
            for (int g = 0; g < 2; g++) {
                uint32_t bo = (uint32_t)((a_row + g * 16) * 128 + (k + a_kc8) * 2);
                ldsm4(al[g][0], al[g][1], al[g][2], al[g][3], sb + ST_AL + SWZ128(bo));
            }
            #pragma unroll
            for (int mt = 0; mt < 2; mt++)
                #pragma unroll
                for (int nt = 0; nt < 8; nt++)
                    mma16816(acc[mt][nt], al[mt], &bh[nt >> 1][(nt & 1) * 2]);
            #pragma unroll
            for (int j = 0; j < 4; j++) {
                uint32_t bo = (uint32_t)((b_nbase + j * 16) * 128 + (k + b_kc8) * 2);
                ldsm4(bl[j][0], bl[j][1], bl[j][2], bl[j][3], sb + ST_BL + SWZ128(bo));
            }
            #pragma unroll
            for (int mt = 0; mt < 2; mt++)
                #pragma unroll
                for (int nt = 0; nt < 8; nt++)
                    mma16816(acc[mt][nt], ah[mt], &bl[nt >> 1][(nt & 1) * 2]);
        }
        __syncthreads();
        if (i + 2 < NCHUNK)
            load_chunk512(sb, brow, (i + 2) * KC, tid, Ahi, Alo, Bhi, Blo);
        asm volatile("cp.async.commit_group;" ::: "memory");
    }

    int col = wn * 64 + 2 * (lane & 3);
    #pragma unroll
    for (int mt = 0; mt < 2; mt++) {
        int r0 = brow + wm * 32 + mt * 16 + (lane >> 2);
        int r1 = r0 + 8;
        #pragma unroll
        for (int nt = 0; nt < 8; nt++) {
            float2 v0 = make_float2(acc[mt][nt][0], acc[mt][nt][1]);
            float2 v1 = make_float2(acc[mt][nt][2], acc[mt][nt][3]);
            if (do_relu) {
                v0.x = fmaxf(v0.x, 0.f); v0.y = fmaxf(v0.y, 0.f);
                v1.x = fmaxf(v1.x, 0.f); v1.y = fmaxf(v1.y, 0.f);
            }
            if (r0 < m_store)
                *reinterpret_cast<float2*>(&C[(size_t)r0 * HID + col + nt * 8]) = v0;
            if (r1 < m_store)
                *reinterpret_cast<float2*>(&C[(size_t)r1 * HID + col + nt * 8]) = v1;
        }
    }
}

// ---------------- launch ----------------
extern "C" void kernel_launch(void* const* d_in, const int* in_sizes, int n_in,
                              void* d_out, int out_size) {
    const int*   edge_index = nullptr;
    const int*   edge_type  = nullptr;
    const float* emb        = nullptr;
    const float* bases      = nullptr;
    const float* coeffs     = nullptr;
    const float* selfw      = nullptr;
    for (int i = 0; i < n_in; i++) {
        switch (in_sizes[i]) {
            case 2 * NEDGES:             edge_index = (const int*)d_in[i]; break;
            case NEDGES:                 edge_type  = (const int*)d_in[i]; break;
            case NNODES * HID:           emb        = (const float*)d_in[i]; break;
            case 2 * NBASES * HID * HID: bases      = (const float*)d_in[i]; break;
            case 2 * NREL * NBASES:      coeffs     = (const float*)d_in[i]; break;
            case 2 * HID * HID:          selfw      = (const float*)d_in[i]; break;
            default: break;
        }
    }
    const int* srcp = edge_index;
    const int* dstp = edge_index + NEDGES;
    float* outp = (float*)d_out;

    // one-time resources (created on the pre-capture correctness call)
    static cudaStream_t s1 = nullptr;
    static cudaEvent_t e0 = nullptr, e1 = nullptr, e2 = nullptr;
    if (!s1) {
        cudaStreamCreateWithFlags(&s1, cudaStreamNonBlocking);
        cudaEventCreateWithFlags(&e0, cudaEventDisableTiming);
        cudaEventCreateWithFlags(&e1, cudaEventDisableTiming);
        cudaEventCreateWithFlags(&e2, cudaEventDisableTiming);
    }

    int* deg_p;
    __nv_bfloat16 *ahi_p, *alo_p, *bhi_p, *blo_p;
    float* x1_p;
    cudaGetSymbolAddress((void**)&deg_p, g_deg);
    cudaGetSymbolAddress((void**)&ahi_p, g_Ahi);
    cudaGetSymbolAddress((void**)&alo_p, g_Alo);
    cudaGetSymbolAddress((void**)&bhi_p, g_Bhi);
    cudaGetSymbolAddress((void**)&blo_p, g_Blo);
    cudaGetSymbolAddress((void**)&x1_p, g_x1);

    cudaFuncSetAttribute(mma_gemm_kernel, cudaFuncAttributeMaxDynamicSharedMemorySize, GEMM_SMEM);

    dim3 wsgrid(KTOT / 32, HID / 32);
    dim3 wsblk(32, 32);
    int ggrid = 391;

    // fork point for the independent weight-prep chain
    cudaEventRecord(e0, 0);

    // main chain (stream 0): CSR + agg0
    cudaMemsetAsync(deg_p, 0, NNODES * sizeof(int), 0);
    hist_kernel<<<(NEDGES + 255) / 256, 256>>>(dstp);
    scan_kernel<<<1, 1024>>>();
    scatter_kernel<<<(NEDGES + 255) / 256, 256>>>(srcp, dstp, edge_type);
    agg_kernel<<<NNODES, HID>>>(emb);

    // side chain (s1): weight prep for both layers, overlapped with the above
    cudaStreamWaitEvent(s1, e0, 0);
    wcat_kernel<<<KTOT, HID, 0, s1>>>(bases, coeffs, selfw, 0);
    wsplit_kernel<<<wsgrid, wsblk, 0, s1>>>(0);
    cudaEventRecord(e1, s1);
    wcat_kernel<<<KTOT, HID, 0, s1>>>(bases, coeffs, selfw, 1);
    wsplit_kernel<<<wsgrid, wsblk, 0, s1>>>(1);
    cudaEventRecord(e2, s1);

    // layer 0 GEMM: needs agg0 (stream 0) + wsplit0 (e1)
    cudaStreamWaitEvent(0, e1, 0);
    mma_gemm_kernel<<<ggrid, 512, GEMM_SMEM>>>(ahi_p, alo_p,
                                               bhi_p, blo_p, x1_p, NNODES, 1);

    // layer 1
    agg_kernel<<<NNODES, HID>>>(x1_p);
    cudaStreamWaitEvent(0, e2, 0);
    mma_gemm_kernel<<<ggrid, 512, GEMM_SMEM>>>(ahi_p, alo_p,
                                               bhi_p + (size_t)HID * KTOT,
                                               blo_p + (size_t)HID * KTOT, outp, NNODES, 0);

    (void)out_size;
}